// round 7
// baseline (speedup 1.0000x reference)
#include <cuda_runtime.h>
#include <cuda_bf16.h>
#include <math.h>
#include <stdint.h>

#define T_LEN 1016
#define TB 8
#define NBLK 127

// ---------------- scratch layout (float units) -------------------------------------
constexpr size_t OFF_WC_HI  = 0;
constexpr size_t OFF_WC_LO  = OFF_WC_HI  + 2097152;
constexpr size_t OFF_FT_HI  = OFF_WC_LO  + 2097152;
constexpr size_t OFF_FT_LO  = OFF_FT_HI  + 131072;
constexpr size_t OFF_BR_HI  = OFF_FT_LO  + 131072;
constexpr size_t OFF_BR_LO  = OFF_BR_HI  + 1048576;
constexpr size_t OFF_B2_HI  = OFF_BR_LO  + 1048576;
constexpr size_t OFF_B2_LO  = OFF_B2_HI  + 1048576;
constexpr size_t OFF_CACTS  = OFF_B2_LO  + 1048576;
constexpr size_t OFF_WOT    = OFF_CACTS  + 2080768;
constexpr size_t OFF_WET    = OFF_WOT    + 65536;
constexpr size_t OFF_X0     = OFF_WET    + 65536;
constexpr size_t OFF_X1     = OFF_X0     + 65024;
constexpr size_t OFF_Q      = OFF_X1     + 65024;
constexpr size_t OFF_WSKT   = OFF_Q      + 1024;
constexpr size_t OFF_WRST   = OFF_WSKT   + 262144;
constexpr size_t SCRATCH_SZ = OFF_WRST + 61440;

__device__ __align__(1024) float g_scratch[SCRATCH_SZ];
__device__ unsigned g_bar;

// ---------------- PTX helpers -------------------------------------------------------
__device__ __forceinline__ uint32_t s2u(const void* p) {
    uint32_t a;
    asm("{ .reg .u64 t; cvta.to.shared.u64 t, %1; cvt.u32.u64 %0, t; }" : "=r"(a) : "l"(p));
    return a;
}
__device__ __forceinline__ void cp16(uint32_t dst, const void* src) {
    asm volatile("cp.async.cg.shared.global [%0], [%1], 16;" :: "r"(dst), "l"(src));
}
#define CP_COMMIT() asm volatile("cp.async.commit_group;" ::: "memory")

__device__ __forceinline__ void ldsm4(uint32_t* r, uint32_t a) {
    asm volatile("ldmatrix.sync.aligned.m8n8.x4.shared.b16 {%0,%1,%2,%3}, [%4];"
                 : "=r"(r[0]), "=r"(r[1]), "=r"(r[2]), "=r"(r[3]) : "r"(a));
}
__device__ __forceinline__ void ldsm4t(uint32_t* r, uint32_t a) {
    asm volatile("ldmatrix.sync.aligned.m8n8.x4.trans.shared.b16 {%0,%1,%2,%3}, [%4];"
                 : "=r"(r[0]), "=r"(r[1]), "=r"(r[2]), "=r"(r[3]) : "r"(a));
}
__device__ __forceinline__ void mma_bf16(float* c, const uint32_t* a, const uint32_t* b) {
    asm volatile("mma.sync.aligned.m16n8k16.row.col.f32.bf16.bf16.f32 "
                 "{%0,%1,%2,%3}, {%4,%5,%6,%7}, {%8,%9}, {%0,%1,%2,%3};"
                 : "+f"(c[0]), "+f"(c[1]), "+f"(c[2]), "+f"(c[3])
                 : "r"(a[0]), "r"(a[1]), "r"(a[2]), "r"(a[3]), "r"(b[0]), "r"(b[1]));
}

// K64 k-major tile: 128 rows x 64 bf16 (128B rows), kk = 16B chunk 0..7
__device__ __forceinline__ uint32_t off_km64(int row, int kk) {
    return (uint32_t)(row * 128 + ((kk ^ (row & 7)) << 4));
}
// K64 trans tile: 64 k-rows x 128 m (256B rows), mc = 16B chunk 0..15
__device__ __forceinline__ uint32_t off_tr64(int k, int mc) {
    return (uint32_t)(k * 256 + ((mc ^ (k & 7)) << 4));
}
__device__ __forceinline__ uint32_t bpack(float x, float y) {
    uint32_t lo = (uint32_t)__bfloat16_as_ushort(__float2bfloat16(x));
    uint32_t hi = (uint32_t)__bfloat16_as_ushort(__float2bfloat16(y));
    return lo | (hi << 16);
}

// ---------------- transposes / splits ------------------------------------------------
__global__ void k_transpose(const float* __restrict__ in, float* __restrict__ out,
                            int R, int C)
{
    __shared__ float tile[32][33];
    int c0 = blockIdx.x * 32, r0 = blockIdx.y * 32;
    int x = threadIdx.x, y = threadIdx.y;
#pragma unroll
    for (int i = 0; i < 32; i += 8)
        tile[y + i][x] = in[(size_t)(r0 + y + i) * C + c0 + x];
    __syncthreads();
#pragma unroll
    for (int i = 0; i < 32; i += 8)
        out[(size_t)(c0 + y + i) * R + r0 + x] = tile[x][y + i];
}

__global__ void k_transpose_b(const float* __restrict__ in, float* __restrict__ out,
                              int R, int C, size_t inL, size_t outL)
{
    __shared__ float tile[32][33];
    int l = blockIdx.z;
    const float* ip = in + (size_t)l * inL;
    float* op = out + (size_t)l * outL;
    int c0 = blockIdx.x * 32, r0 = blockIdx.y * 32;
    int x = threadIdx.x, y = threadIdx.y;
#pragma unroll
    for (int i = 0; i < 32; i += 8)
        tile[y + i][x] = ip[(size_t)(r0 + y + i) * C + c0 + x];
    __syncthreads();
#pragma unroll
    for (int i = 0; i < 32; i += 8)
        op[(size_t)(c0 + y + i) * R + r0 + x] = tile[x][y + i];
}

__global__ void k_tsplit(const float* __restrict__ in, __nv_bfloat16* __restrict__ hi,
                         __nv_bfloat16* __restrict__ lo, int R, int C)
{
    __shared__ float tile[32][33];
    int c0 = blockIdx.x * 32, r0 = blockIdx.y * 32;
    int x = threadIdx.x, y = threadIdx.y;
#pragma unroll
    for (int i = 0; i < 32; i += 8)
        tile[y + i][x] = in[(size_t)(r0 + y + i) * C + c0 + x];
    __syncthreads();
#pragma unroll
    for (int i = 0; i < 32; i += 8) {
        float v = tile[x][y + i];
        size_t o = (size_t)(c0 + y + i) * R + r0 + x;
        __nv_bfloat16 h = __float2bfloat16(v);
        hi[o] = h;
        lo[o] = __float2bfloat16(v - __bfloat162float(h));
    }
}

__global__ void k_split4(const float* __restrict__ in, __nv_bfloat16* __restrict__ hi,
                         __nv_bfloat16* __restrict__ lo, int n4)
{
    int i = blockIdx.x * 256 + threadIdx.x;
    if (i >= n4) return;
    float4 v = reinterpret_cast<const float4*>(in)[i];
    __nv_bfloat16 h0 = __float2bfloat16(v.x), h1 = __float2bfloat16(v.y);
    __nv_bfloat16 h2 = __float2bfloat16(v.z), h3 = __float2bfloat16(v.w);
    uint2 vh = make_uint2(
        (uint32_t)__bfloat16_as_ushort(h0) | ((uint32_t)__bfloat16_as_ushort(h1) << 16),
        (uint32_t)__bfloat16_as_ushort(h2) | ((uint32_t)__bfloat16_as_ushort(h3) << 16));
    uint2 vl = make_uint2(bpack(v.x - __bfloat162float(h0), v.y - __bfloat162float(h1)),
                          bpack(v.z - __bfloat162float(h2), v.w - __bfloat162float(h3)));
    reinterpret_cast<uint2*>(hi)[i] = vh;
    reinterpret_cast<uint2*>(lo)[i] = vl;
}

// ---------------- mma.sync split-bf16 GEMM, 512 thr, K64 x 3-stage pipeline ---------
__global__ __launch_bounds__(512)
void k_gemm_tc(const __nv_bfloat16* __restrict__ Ahi, const __nv_bfloat16* __restrict__ Alo,
               const float* __restrict__ Af32, int Mg, int afp32,
               const __nv_bfloat16* __restrict__ Bhi, const __nv_bfloat16* __restrict__ Blo,
               int K, int mode, const float* __restrict__ bias,
               float* __restrict__ outF,
               __nv_bfloat16* __restrict__ outHi, __nv_bfloat16* __restrict__ outLo)
{
    extern __shared__ char smem[];
    uint32_t sb = s2u(smem);
    const int tid = threadIdx.x;
    const int wid = tid >> 5, lane = tid & 31;
    const int bm = blockIdx.x * 128, bn = blockIdx.y * 128;
    const int wm = (wid & 3) * 32, wn = (wid >> 2) * 32;
    const uint32_t STG = 65536;   // A_HI 0 | A_LO 16384 | B_HI 32768 | B_LO 49152

    float acc[2][4][4];
#pragma unroll
    for (int mt = 0; mt < 2; mt++)
#pragma unroll
        for (int nt = 0; nt < 4; nt++)
#pragma unroll
            for (int i = 0; i < 4; i++) acc[mt][nt][i] = 0.0f;

    const int nsteps = K >> 6;
    float4 pre[4];

    auto ldg_pre = [&](int k0) {
#pragma unroll
        for (int i = 0; i < 4; i++) {
            int u = tid + i * 512;
            int k = u >> 5, f4 = u & 31;
            pre[i] = *reinterpret_cast<const float4*>(Af32 + (size_t)(k0 + k) * Mg + bm + f4 * 4);
        }
    };
    auto sts_pre = [&](int s) {
#pragma unroll
        for (int i = 0; i < 4; i++) {
            int u = tid + i * 512;
            int k = u >> 5, f4 = u & 31;
            float4 v = pre[i];
            __nv_bfloat16 h0 = __float2bfloat16(v.x), h1 = __float2bfloat16(v.y);
            __nv_bfloat16 h2 = __float2bfloat16(v.z), h3 = __float2bfloat16(v.w);
            uint32_t hi01 = (uint32_t)__bfloat16_as_ushort(h0) |
                            ((uint32_t)__bfloat16_as_ushort(h1) << 16);
            uint32_t hi23 = (uint32_t)__bfloat16_as_ushort(h2) |
                            ((uint32_t)__bfloat16_as_ushort(h3) << 16);
            uint32_t lo01 = bpack(v.x - __bfloat162float(h0), v.y - __bfloat162float(h1));
            uint32_t lo23 = bpack(v.z - __bfloat162float(h2), v.w - __bfloat162float(h3));
            int mc = f4 >> 1, half = f4 & 1;
            uint32_t a = (uint32_t)s * STG + off_tr64(k, mc) + half * 8;
            *reinterpret_cast<uint2*>(smem + a) = make_uint2(hi01, hi23);
            *reinterpret_cast<uint2*>(smem + 16384 + a) = make_uint2(lo01, lo23);
        }
    };
    auto fill_b = [&](int s, int k0) {
        uint32_t base = sb + (uint32_t)s * STG;
#pragma unroll
        for (int i = 0; i < 2; i++) {
            int idx = tid + i * 512;
            int row = idx >> 3, kk = idx & 7;
            uint32_t d = off_km64(row, kk);
            cp16(base + 32768 + d, Bhi + (size_t)(bn + row) * K + k0 + kk * 8);
            cp16(base + 49152 + d, Blo + (size_t)(bn + row) * K + k0 + kk * 8);
        }
    };
    auto fill_ab = [&](int s, int k0) {
        uint32_t base = sb + (uint32_t)s * STG;
#pragma unroll
        for (int i = 0; i < 2; i++) {
            int idx = tid + i * 512;
            int row = idx >> 3, kk = idx & 7;
            uint32_t d = off_km64(row, kk);
            cp16(base + d,         Ahi + (size_t)(bm + row) * K + k0 + kk * 8);
            cp16(base + 16384 + d, Alo + (size_t)(bm + row) * K + k0 + kk * 8);
            cp16(base + 32768 + d, Bhi + (size_t)(bn + row) * K + k0 + kk * 8);
            cp16(base + 49152 + d, Blo + (size_t)(bn + row) * K + k0 + kk * 8);
        }
    };

    // ---- prologue: stages 0 and 1 ----
    if (afp32) {
        ldg_pre(0);
        sts_pre(0);
        ldg_pre(64);
        fill_b(0, 0);  CP_COMMIT();
        fill_b(1, 64); CP_COMMIT();
    } else {
        fill_ab(0, 0);  CP_COMMIT();
        fill_ab(1, 64); CP_COMMIT();
    }

    int sc = 0;
    for (int it = 0; it < nsteps; it++) {
        int sn = sc + 1; if (sn == 3) sn = 0;
        int sf = sn + 1; if (sf == 3) sf = 0;

        if (it < nsteps - 1)
            asm volatile("cp.async.wait_group 1;" ::: "memory");
        else
            asm volatile("cp.async.wait_group 0;" ::: "memory");
        __syncthreads();

        if (afp32) {
            if (it + 1 < nsteps) sts_pre(sn);
            if (it + 2 < nsteps) {
                ldg_pre((it + 2) * 64);
                fill_b(sf, (it + 2) * 64);
                CP_COMMIT();
            }
        } else if (it + 2 < nsteps) {
            fill_ab(sf, (it + 2) * 64);
            CP_COMMIT();
        }

        // ---- compute stage sc: 4 x k16 ----
        uint32_t base = sb + (uint32_t)sc * STG;
#pragma unroll
        for (int s = 0; s < 4; s++) {
            const int kk0 = s * 2;
            uint32_t af[2][2][4];
#pragma unroll
            for (int mt = 0; mt < 2; mt++) {
                if (afp32) {
                    int k  = s * 16 + ((lane >> 4) << 3) + (lane & 7);
                    int mc = ((wm + mt * 16) >> 3) + ((lane >> 3) & 1);
                    uint32_t ad = off_tr64(k, mc);
                    ldsm4t(af[mt][0], base + ad);
                    ldsm4t(af[mt][1], base + 16384 + ad);
                } else {
                    int r2 = wm + mt * 16 + (lane & 15);
                    int k2 = kk0 + (lane >> 4);
                    uint32_t ad = off_km64(r2, k2);
                    ldsm4(af[mt][0], base + ad);
                    ldsm4(af[mt][1], base + 16384 + ad);
                }
            }
            uint32_t bh[4][2], bl[4][2];
#pragma unroll
            for (int p = 0; p < 2; p++) {
                int r2 = wn + p * 16 + ((lane >> 4) << 3) + (lane & 7);
                int k2 = kk0 + ((lane >> 3) & 1);
                uint32_t bd = off_km64(r2, k2);
                uint32_t r[4];
                ldsm4(r, base + 32768 + bd);
                bh[2 * p][0] = r[0]; bh[2 * p][1] = r[1];
                bh[2 * p + 1][0] = r[2]; bh[2 * p + 1][1] = r[3];
                ldsm4(r, base + 49152 + bd);
                bl[2 * p][0] = r[0]; bl[2 * p][1] = r[1];
                bl[2 * p + 1][0] = r[2]; bl[2 * p + 1][1] = r[3];
            }
#pragma unroll
            for (int mt = 0; mt < 2; mt++)
#pragma unroll
                for (int nt = 0; nt < 4; nt++) {
                    mma_bf16(acc[mt][nt], af[mt][0], bh[nt]);
                    mma_bf16(acc[mt][nt], af[mt][0], bl[nt]);
                    mma_bf16(acc[mt][nt], af[mt][1], bh[nt]);
                }
        }
        sc = sn;
    }
    __syncthreads();

    // ---- stage D (128x128) to smem, stride 129 ----
    float* sd = reinterpret_cast<float*>(smem);
#pragma unroll
    for (int mt = 0; mt < 2; mt++)
#pragma unroll
        for (int nt = 0; nt < 4; nt++) {
            int r = wm + mt * 16 + (lane >> 2);
            int c = wn + nt * 8 + (lane & 3) * 2;
            sd[r * 129 + c]           = acc[mt][nt][0];
            sd[r * 129 + c + 1]       = acc[mt][nt][1];
            sd[(r + 8) * 129 + c]     = acc[mt][nt][2];
            sd[(r + 8) * 129 + c + 1] = acc[mt][nt][3];
        }
    __syncthreads();

    if (mode == 0) {
        int bo = bm >> 4;
        for (int u = tid; u < T_LEN; u += 512) {
            int m = u >> 3, p = u & 7;
            uint4 vh, vl;
            __nv_bfloat16* hp = (__nv_bfloat16*)&vh;
            __nv_bfloat16* lp = (__nv_bfloat16*)&vl;
#pragma unroll
            for (int ol = 0; ol < 8; ol++) {
                float v = sd[(ol * 16 + p + 8) * 129 + m] +
                          sd[(ol * 16 + p) * 129 + m + 1] + bias[bo + ol];
                __nv_bfloat16 h = __float2bfloat16(v);
                hp[ol] = h;
                lp[ol] = __float2bfloat16(v - __bfloat162float(h));
            }
            *reinterpret_cast<uint4*>(outHi + (size_t)u * 2048 + bo) = vh;
            *reinterpret_cast<uint4*>(outLo + (size_t)u * 2048 + bo) = vl;
        }
    } else if (mode == 1) {
        int mg = (tid & 31) * 4;
        int nl = tid >> 5;
        for (int n0 = 0; n0 < 128; n0 += 16) {
            int n = n0 + nl;
            uint2 vh, vl;
            __nv_bfloat16* hp = (__nv_bfloat16*)&vh;
            __nv_bfloat16* lp = (__nv_bfloat16*)&vl;
#pragma unroll
            for (int j = 0; j < 4; j++) {
                float v = sd[(mg + j) * 129 + n] + bias[bm + mg + j];
                __nv_bfloat16 h = __float2bfloat16(v);
                hp[j] = h;
                lp[j] = __float2bfloat16(v - __bfloat162float(h));
            }
            *reinterpret_cast<uint2*>(outHi + (size_t)(bn + n) * 2048 + bm + mg) = vh;
            *reinterpret_cast<uint2*>(outLo + (size_t)(bn + n) * 2048 + bm + mg) = vl;
        }
    } else {
        int mo = tid >> 7, n = tid & 127;
        int gn = bn + n;
        if (gn < T_LEN) {
            for (int m0 = 0; m0 < 128; m0 += 4) {
                int m = m0 + mo;
                outF[(size_t)(bm + m) * T_LEN + gn] = sd[m * 129 + n] + bias[bm + m];
            }
        }
    }
}

// ---------------- barrier reset ------------------------------------------------------
__global__ void k_reset() { g_bar = 0; }

// ---------------- fused persistent tail ---------------------------------------------
__global__ __launch_bounds__(256)
void k_tail(const float* __restrict__ audio, const float* __restrict__ embed,
            const float* __restrict__ w_dil_all, const float* __restrict__ b_dil_all,
            const float* __restrict__ b_res_all, const float* __restrict__ b_skip_all,
            float* __restrict__ out, int write_q)
{
    __shared__ float WD[4096];
    __shared__ float XS0[64 * TB];
    __shared__ float XS1[64 * TB];
    __shared__ float IA[64 * TB];
    __shared__ float ACT[64 * TB];
    __shared__ float HS[256 * TB];
    __shared__ float HS2[256 * TB];
    __shared__ int QS[TB];

    const int tid = threadIdx.x;
    const int t0 = blockIdx.x * TB;
    unsigned bar_target = 0;

    if (tid < TB) {
        int t = t0 + tid;
        float x = audio[t];
        float xc = fminf(1.0f, fmaxf(-1.0f, x));
        float s  = (xc > 0.0f) ? 1.0f : ((xc < 0.0f) ? -1.0f : 0.0f);
        float num = log1pf(__fmul_rn(255.0f, fabsf(xc)));
        float den = log1pf(255.0f);
        float m = __fdiv_rn(__fmul_rn(s, num), den);
        float v = __fadd_rn(__fmul_rn(__fmul_rn(__fadd_rn(m, 1.0f), 0.5f), 255.0f), 0.5f);
        v = fminf(255.0f, fmaxf(0.0f, v));
        int q = (int)v;
        QS[tid] = q;
        if (write_q) out[(size_t)256 * T_LEN + t] = (float)q;
    }
    __syncthreads();

    {
        float* X0 = g_scratch + OFF_X0;
        for (int idx = tid; idx < 64 * TB; idx += 256) {
            int j = idx / TB, tt = idx % TB;
            X0[(size_t)j * T_LEN + t0 + tt] = embed[QS[tt] * 64 + j];
        }
    }

    auto gbar = [&]() {
        bar_target += NBLK;
        __syncthreads();
        __threadfence();
        if (tid == 0) {
            atomicAdd(&g_bar, 1u);
            unsigned v;
            do {
                asm volatile("ld.global.acquire.gpu.u32 %0, [%1];"
                             : "=r"(v) : "l"(&g_bar) : "memory");
            } while (v < bar_target);
        }
        __syncthreads();
    };
    gbar();

    float s_acc[TB];
#pragma unroll
    for (int tt = 0; tt < TB; tt++) s_acc[tt] = 0.0f;

    const int c  = tid & 127;
    const int th = tid >> 7;

    for (int layer = 0; layer < 16; layer++) {
        const int d = 1 << (layer & 7);
        const float* xin  = g_scratch + ((layer & 1) ? OFF_X1 : OFF_X0);
        float*       xout = g_scratch + ((layer & 1) ? OFF_X0 : OFF_X1);
        const float* cond = g_scratch + OFF_CACTS + (size_t)layer * 128 * T_LEN;
        const float* wd   = w_dil_all + (size_t)layer * 16384;

        for (int idx = tid; idx < 64 * TB; idx += 256) {
            int j = idx / TB, tt = idx % TB;
            int ta = t0 - d + tt;
            XS0[idx] = (ta >= 0) ? xin[(size_t)j * T_LEN + ta] : 0.0f;
            XS1[idx] = xin[(size_t)j * T_LEN + t0 + tt];
        }

        float a4[4] = {0.0f, 0.0f, 0.0f, 0.0f};
        for (int jc = 0; jc < 64; jc += 16) {
            __syncthreads();
            for (int idx = tid; idx < 4096; idx += 256) {
                int cc = idx >> 5, inner = idx & 31;
                WD[inner * 128 + cc] = wd[cc * 128 + jc * 2 + inner];
            }
            __syncthreads();
#pragma unroll
            for (int jj = 0; jj < 16; jj++) {
                float w0 = WD[(2 * jj) * 128 + c];
                float w1 = WD[(2 * jj + 1) * 128 + c];
                int j = jc + jj;
                float4 x0 = *reinterpret_cast<const float4*>(&XS0[j * TB + th * 4]);
                float4 x1 = *reinterpret_cast<const float4*>(&XS1[j * TB + th * 4]);
                a4[0] += w0 * x0.x + w1 * x1.x;
                a4[1] += w0 * x0.y + w1 * x1.y;
                a4[2] += w0 * x0.z + w1 * x1.z;
                a4[3] += w0 * x0.w + w1 * x1.w;
            }
        }

        {
            float bd = b_dil_all[layer * 128 + c];
#pragma unroll
            for (int i = 0; i < 4; i++) {
                int t = t0 + th * 4 + i;
                a4[i] += bd + cond[(size_t)c * T_LEN + t];
            }
        }
        __syncthreads();
        if (c >= 64) {
#pragma unroll
            for (int i = 0; i < 4; i++) IA[(c - 64) * TB + th * 4 + i] = a4[i];
        }
        __syncthreads();
        if (c < 64) {
#pragma unroll
            for (int i = 0; i < 4; i++) {
                int tt = th * 4 + i;
                float g = IA[c * TB + tt];
                float sg = 1.0f / (1.0f + expf(-g));
                ACT[c * TB + tt] = tanhf(a4[i]) * sg;
            }
        }
        __syncthreads();

        if (layer < 15) {
            const float* wr = g_scratch + OFF_WRST + (size_t)layer * 4096;
            int c2 = tid & 63, qq = tid >> 6;
            float r2[2] = {0.0f, 0.0f};
            for (int k = 0; k < 64; k++) {
                float w = wr[k * 64 + c2];
#pragma unroll
                for (int i = 0; i < 2; i++)
                    r2[i] += w * ACT[k * TB + qq * 2 + i];
            }
            float br = b_res_all[layer * 64 + c2];
#pragma unroll
            for (int i = 0; i < 2; i++) {
                int t = t0 + qq * 2 + i;
                xout[(size_t)c2 * T_LEN + t] = xin[(size_t)c2 * T_LEN + t] + r2[i] + br;
            }
        }

        {
            const float* wsk = g_scratch + OFF_WSKT + (size_t)layer * 16384;
            for (int k = 0; k < 64; k++) {
                float w = wsk[k * 256 + tid];
                float4 a0 = *reinterpret_cast<const float4*>(&ACT[k * TB]);
                float4 a1 = *reinterpret_cast<const float4*>(&ACT[k * TB + 4]);
                s_acc[0] += w * a0.x; s_acc[1] += w * a0.y;
                s_acc[2] += w * a0.z; s_acc[3] += w * a0.w;
                s_acc[4] += w * a1.x; s_acc[5] += w * a1.y;
                s_acc[6] += w * a1.z; s_acc[7] += w * a1.w;
            }
            float bs = b_skip_all[layer * 256 + tid];
#pragma unroll
            for (int tt = 0; tt < TB; tt++) s_acc[tt] += bs;
        }

        if (layer < 15) gbar();
    }

    {
        __syncthreads();
#pragma unroll
        for (int tt = 0; tt < TB; tt++) HS[tid * TB + tt] = fmaxf(s_acc[tt], 0.0f);
        __syncthreads();

        const float* wo = g_scratch + OFF_WOT;
        float h[TB];
#pragma unroll
        for (int tt = 0; tt < TB; tt++) h[tt] = 0.0f;
        for (int cc = 0; cc < 256; cc++) {
            float w = wo[cc * 256 + tid];
            float4 v0 = *reinterpret_cast<const float4*>(&HS[cc * TB]);
            float4 v1 = *reinterpret_cast<const float4*>(&HS[cc * TB + 4]);
            h[0] += w * v0.x; h[1] += w * v0.y; h[2] += w * v0.z; h[3] += w * v0.w;
            h[4] += w * v1.x; h[5] += w * v1.y; h[6] += w * v1.z; h[7] += w * v1.w;
        }
#pragma unroll
        for (int tt = 0; tt < TB; tt++) HS2[tid * TB + tt] = fmaxf(h[tt], 0.0f);
        __syncthreads();

        const float* we = g_scratch + OFF_WET;
        float h2[TB];
#pragma unroll
        for (int tt = 0; tt < TB; tt++) h2[tt] = 0.0f;
        for (int cc = 0; cc < 256; cc++) {
            float w = we[cc * 256 + tid];
            float4 v0 = *reinterpret_cast<const float4*>(&HS2[cc * TB]);
            float4 v1 = *reinterpret_cast<const float4*>(&HS2[cc * TB + 4]);
            h2[0] += w * v0.x; h2[1] += w * v0.y; h2[2] += w * v0.z; h2[3] += w * v0.w;
            h2[4] += w * v1.x; h2[5] += w * v1.y; h2[6] += w * v1.z; h2[7] += w * v1.w;
        }

        if (blockIdx.x == 0) out[(size_t)tid * T_LEN] = 0.0f;
#pragma unroll
        for (int tt = 0; tt < TB; tt++) {
            int t = t0 + tt;
            if (t + 1 < T_LEN) out[(size_t)tid * T_LEN + t + 1] = h2[tt];
        }
    }
}

// ---------------- launch -------------------------------------------------------------
extern "C" void kernel_launch(void* const* d_in, const int* in_sizes, int n_in,
                              void* d_out, int out_size)
{
    const float* features = (const float*)d_in[0];
    const float* audio    = (const float*)d_in[1];
    const float* w_up     = (const float*)d_in[2];
    const float* b_up     = (const float*)d_in[3];
    const float* w_cond   = (const float*)d_in[4];
    const float* b_cond   = (const float*)d_in[5];
    const float* embed    = (const float*)d_in[6];
    const float* w_dil    = (const float*)d_in[7];
    const float* b_dil    = (const float*)d_in[8];
    const float* w_res    = (const float*)d_in[9];
    const float* b_res    = (const float*)d_in[10];
    const float* w_skip   = (const float*)d_in[11];
    const float* b_skip   = (const float*)d_in[12];
    const float* w_out    = (const float*)d_in[13];
    const float* w_end    = (const float*)d_in[14];
    float* out = (float*)d_out;

    float* scr = nullptr;
    cudaGetSymbolAddress((void**)&scr, g_scratch);

    __nv_bfloat16* WC_HI = (__nv_bfloat16*)(scr + OFF_WC_HI);
    __nv_bfloat16* WC_LO = (__nv_bfloat16*)(scr + OFF_WC_LO);
    __nv_bfloat16* FT_HI = (__nv_bfloat16*)(scr + OFF_FT_HI);
    __nv_bfloat16* FT_LO = (__nv_bfloat16*)(scr + OFF_FT_LO);
    __nv_bfloat16* BR_HI = (__nv_bfloat16*)(scr + OFF_BR_HI);
    __nv_bfloat16* BR_LO = (__nv_bfloat16*)(scr + OFF_BR_LO);
    __nv_bfloat16* B2_HI = (__nv_bfloat16*)(scr + OFF_B2_HI);
    __nv_bfloat16* B2_LO = (__nv_bfloat16*)(scr + OFF_B2_LO);

    cudaFuncSetAttribute(k_gemm_tc, cudaFuncAttributeMaxDynamicSharedMemorySize, 196608);

    static cudaStream_t sB = nullptr;
    static cudaEvent_t evF = nullptr, evJ = nullptr;
    if (sB == nullptr) {
        cudaStreamCreateWithFlags(&sB, cudaStreamNonBlocking);
        cudaEventCreateWithFlags(&evF, cudaEventDisableTiming);
        cudaEventCreateWithFlags(&evJ, cudaEventDisableTiming);
    }

    int write_q = (out_size >= 256 * T_LEN + T_LEN) ? 1 : 0;

    dim3 tb(32, 8);
    // [1] features split (needed by upsample)
    k_tsplit<<<dim3(4, 64), tb>>>(features, FT_HI, FT_LO, 2048, 128);

    // fork side stream: prep that upsample doesn't need
    cudaEventRecord(evF, 0);
    cudaStreamWaitEvent(sB, evF, 0);
    k_split4<<<(2048 * 2048 / 4 + 255) / 256, 256, 0, sB>>>(w_cond, WC_HI, WC_LO,
                                                            2048 * 2048 / 4);   // [2]
    k_transpose<<<dim3(8, 8), tb, 0, sB>>>(w_out, scr + OFF_WOT, 256, 256);     // [3]

    // [4] upsample GEMM (ncu target)
    k_gemm_tc<<<dim3(256, 1), 512, 196608>>>(nullptr, nullptr, w_up, 32768, 1,
                                             FT_HI, FT_LO, 2048, 0,
                                             b_up, nullptr, BR_HI, BR_LO);

    k_transpose<<<dim3(8, 8), tb, 0, sB>>>(w_end, scr + OFF_WET, 256, 256);
    k_transpose_b<<<dim3(2, 8, 16), tb, 0, sB>>>(w_skip, scr + OFF_WSKT, 256, 64,
                                                 256 * 64, 64 * 256);
    k_transpose_b<<<dim3(2, 2, 15), tb, 0, sB>>>(w_res, scr + OFF_WRST, 64, 64,
                                                 64 * 64, 64 * 64);
    k_reset<<<1, 1, 0, sB>>>();
    cudaEventRecord(evJ, sB);
    cudaStreamWaitEvent(0, evJ, 0);

    // cond GEMM #1 / #2 (legacy stream, after join)
    k_gemm_tc<<<dim3(16, 8), 512, 196608>>>(WC_HI, WC_LO, nullptr, 0, 0,
                                            BR_HI, BR_LO, 2048, 1,
                                            b_cond, nullptr, B2_HI, B2_LO);
    k_gemm_tc<<<dim3(16, 8), 512, 196608>>>(WC_HI, WC_LO, nullptr, 0, 0,
                                            B2_HI, B2_LO, 2048, 2,
                                            b_cond, scr + OFF_CACTS, nullptr, nullptr);

    k_tail<<<NBLK, 256>>>(audio, embed, w_dil, b_dil, b_res, b_skip, out, write_q);
}

// round 8
// speedup vs baseline: 1.1790x; 1.1790x over previous
#include <cuda_runtime.h>
#include <cuda_bf16.h>
#include <math.h>
#include <stdint.h>

#define T_LEN 1016
#define TB 8
#define NBLK 127

// ---------------- scratch layout (float units) -------------------------------------
constexpr size_t OFF_WC_HI  = 0;
constexpr size_t OFF_WC_LO  = OFF_WC_HI  + 2097152;
constexpr size_t OFF_FT_HI  = OFF_WC_LO  + 2097152;
constexpr size_t OFF_FT_LO  = OFF_FT_HI  + 131072;
constexpr size_t OFF_BR_HI  = OFF_FT_LO  + 131072;
constexpr size_t OFF_BR_LO  = OFF_BR_HI  + 1048576;
constexpr size_t OFF_B2_HI  = OFF_BR_LO  + 1048576;
constexpr size_t OFF_B2_LO  = OFF_B2_HI  + 1048576;
constexpr size_t OFF_CACTS  = OFF_B2_LO  + 1048576;
constexpr size_t OFF_WOT    = OFF_CACTS  + 2080768;
constexpr size_t OFF_WET    = OFF_WOT    + 65536;
constexpr size_t OFF_X0     = OFF_WET    + 65536;
constexpr size_t OFF_X1     = OFF_X0     + 65024;
constexpr size_t OFF_WSKT   = OFF_X1     + 65024;
constexpr size_t OFF_WRST   = OFF_WSKT   + 262144;
constexpr size_t SCRATCH_SZ = OFF_WRST + 61440;

__device__ __align__(1024) float g_scratch[SCRATCH_SZ];
__device__ unsigned g_bar;
__device__ unsigned g_bar2;

// ---------------- PTX helpers -------------------------------------------------------
__device__ __forceinline__ uint32_t s2u(const void* p) {
    uint32_t a;
    asm("{ .reg .u64 t; cvta.to.shared.u64 t, %1; cvt.u32.u64 %0, t; }" : "=r"(a) : "l"(p));
    return a;
}
__device__ __forceinline__ void cp16(uint32_t dst, const void* src) {
    asm volatile("cp.async.cg.shared.global [%0], [%1], 16;" :: "r"(dst), "l"(src));
}
#define CP_COMMIT() asm volatile("cp.async.commit_group;" ::: "memory")

__device__ __forceinline__ void ldsm4(uint32_t* r, uint32_t a) {
    asm volatile("ldmatrix.sync.aligned.m8n8.x4.shared.b16 {%0,%1,%2,%3}, [%4];"
                 : "=r"(r[0]), "=r"(r[1]), "=r"(r[2]), "=r"(r[3]) : "r"(a));
}
__device__ __forceinline__ void ldsm4t(uint32_t* r, uint32_t a) {
    asm volatile("ldmatrix.sync.aligned.m8n8.x4.trans.shared.b16 {%0,%1,%2,%3}, [%4];"
                 : "=r"(r[0]), "=r"(r[1]), "=r"(r[2]), "=r"(r[3]) : "r"(a));
}
__device__ __forceinline__ void mma_bf16(float* c, const uint32_t* a, const uint32_t* b) {
    asm volatile("mma.sync.aligned.m16n8k16.row.col.f32.bf16.bf16.f32 "
                 "{%0,%1,%2,%3}, {%4,%5,%6,%7}, {%8,%9}, {%0,%1,%2,%3};"
                 : "+f"(c[0]), "+f"(c[1]), "+f"(c[2]), "+f"(c[3])
                 : "r"(a[0]), "r"(a[1]), "r"(a[2]), "r"(a[3]), "r"(b[0]), "r"(b[1]));
}

__device__ __forceinline__ uint32_t off_km64(int row, int kk) {
    return (uint32_t)(row * 128 + ((kk ^ (row & 7)) << 4));
}
__device__ __forceinline__ uint32_t off_tr64(int k, int mc) {
    return (uint32_t)(k * 256 + ((mc ^ (k & 7)) << 4));
}
__device__ __forceinline__ uint32_t bpack(float x, float y) {
    uint32_t lo = (uint32_t)__bfloat16_as_ushort(__float2bfloat16(x));
    uint32_t hi = (uint32_t)__bfloat16_as_ushort(__float2bfloat16(y));
    return lo | (hi << 16);
}

// ---------------- prep mega-kernel (splits + transposes + barrier resets) -----------
__global__ __launch_bounds__(256)
void k_prep(const float* __restrict__ features, const float* __restrict__ w_cond,
            const float* __restrict__ w_out, const float* __restrict__ w_end,
            const float* __restrict__ w_skip, const float* __restrict__ w_res)
{
    __shared__ float tile[32 * 33];
    const int b = blockIdx.x, tid = threadIdx.x;
    const int x = tid & 31, y = tid >> 5;

    __nv_bfloat16* WC_HI = (__nv_bfloat16*)(g_scratch + OFF_WC_HI);
    __nv_bfloat16* WC_LO = (__nv_bfloat16*)(g_scratch + OFF_WC_LO);
    __nv_bfloat16* FT_HI = (__nv_bfloat16*)(g_scratch + OFF_FT_HI);
    __nv_bfloat16* FT_LO = (__nv_bfloat16*)(g_scratch + OFF_FT_LO);

    auto tr = [&](const float* ip, float* op, int R, int C, int c0, int r0) {
#pragma unroll
        for (int i = 0; i < 32; i += 8)
            tile[(y + i) * 33 + x] = ip[(size_t)(r0 + y + i) * C + c0 + x];
        __syncthreads();
#pragma unroll
        for (int i = 0; i < 32; i += 8)
            op[(size_t)(c0 + y + i) * R + r0 + x] = tile[x * 33 + y + i];
    };

    if (b < 4096) {
        int i = b * 256 + tid;   // 4096*256 = 1048576 float4 = full w_cond
        float4 v = reinterpret_cast<const float4*>(w_cond)[i];
        __nv_bfloat16 h0 = __float2bfloat16(v.x), h1 = __float2bfloat16(v.y);
        __nv_bfloat16 h2 = __float2bfloat16(v.z), h3 = __float2bfloat16(v.w);
        uint2 vh = make_uint2(
            (uint32_t)__bfloat16_as_ushort(h0) | ((uint32_t)__bfloat16_as_ushort(h1) << 16),
            (uint32_t)__bfloat16_as_ushort(h2) | ((uint32_t)__bfloat16_as_ushort(h3) << 16));
        uint2 vl = make_uint2(bpack(v.x - __bfloat162float(h0), v.y - __bfloat162float(h1)),
                              bpack(v.z - __bfloat162float(h2), v.w - __bfloat162float(h3)));
        reinterpret_cast<uint2*>(WC_HI)[i] = vh;
        reinterpret_cast<uint2*>(WC_LO)[i] = vl;
    } else if (b < 4352) {
        int t = b - 4096;                       // features tsplit: R=2048, C=128
        int c0 = (t & 3) * 32, r0 = (t >> 2) * 32;
#pragma unroll
        for (int i = 0; i < 32; i += 8)
            tile[(y + i) * 33 + x] = features[(size_t)(r0 + y + i) * 128 + c0 + x];
        __syncthreads();
#pragma unroll
        for (int i = 0; i < 32; i += 8) {
            float v = tile[x * 33 + y + i];
            size_t o = (size_t)(c0 + y + i) * 2048 + r0 + x;
            __nv_bfloat16 h = __float2bfloat16(v);
            FT_HI[o] = h;
            FT_LO[o] = __float2bfloat16(v - __bfloat162float(h));
        }
    } else if (b < 4416) {
        int t = b - 4352;
        tr(w_out, g_scratch + OFF_WOT, 256, 256, (t & 7) * 32, (t >> 3) * 32);
    } else if (b < 4480) {
        int t = b - 4416;
        tr(w_end, g_scratch + OFF_WET, 256, 256, (t & 7) * 32, (t >> 3) * 32);
    } else if (b < 4736) {
        int t = b - 4480;                       // w_skip: 16 layers, 256x64 -> 64x256
        int l = t >> 4, bx = t & 1, by = (t >> 1) & 7;
        tr(w_skip + (size_t)l * 16384, g_scratch + OFF_WSKT + (size_t)l * 16384,
           256, 64, bx * 32, by * 32);
    } else if (b < 4796) {
        int t = b - 4736;                       // w_res: 15 layers, 64x64 -> 64x64
        int l = t >> 2, bx = t & 1, by = (t >> 1) & 1;
        tr(w_res + (size_t)l * 4096, g_scratch + OFF_WRST + (size_t)l * 4096,
           64, 64, bx * 32, by * 32);
    } else {
        if (tid == 0) { g_bar = 0; g_bar2 = 0; }
    }
}

// ---------------- GEMM core (bf16 A + bf16 B, K64 3-stage pipeline) -----------------
// mode 1: +bias, write hi/lo transposed [n][2048] at col bm; mode 2: fp32 [m][1016]
__device__ __forceinline__ void gemm_core(
    char* smem, uint32_t sb, int tid,
    const __nv_bfloat16* __restrict__ Ahi, const __nv_bfloat16* __restrict__ Alo,
    const __nv_bfloat16* __restrict__ Bhi, const __nv_bfloat16* __restrict__ Blo,
    int K, int bm, int bn, int mode, const float* __restrict__ bias,
    float* __restrict__ outF,
    __nv_bfloat16* __restrict__ outHi, __nv_bfloat16* __restrict__ outLo)
{
    const int wid = tid >> 5, lane = tid & 31;
    const int wm = (wid & 3) * 32, wn = (wid >> 2) * 32;
    const uint32_t STG = 65536;

    float acc[2][4][4];
#pragma unroll
    for (int mt = 0; mt < 2; mt++)
#pragma unroll
        for (int nt = 0; nt < 4; nt++)
#pragma unroll
            for (int i = 0; i < 4; i++) acc[mt][nt][i] = 0.0f;

    const int nsteps = K >> 6;

    auto fill_ab = [&](int s, int k0) {
        uint32_t base = sb + (uint32_t)s * STG;
#pragma unroll
        for (int i = 0; i < 2; i++) {
            int idx = tid + i * 512;
            int row = idx >> 3, kk = idx & 7;
            uint32_t d = off_km64(row, kk);
            cp16(base + d,         Ahi + (size_t)(bm + row) * K + k0 + kk * 8);
            cp16(base + 16384 + d, Alo + (size_t)(bm + row) * K + k0 + kk * 8);
            cp16(base + 32768 + d, Bhi + (size_t)(bn + row) * K + k0 + kk * 8);
            cp16(base + 49152 + d, Blo + (size_t)(bn + row) * K + k0 + kk * 8);
        }
    };

    fill_ab(0, 0);  CP_COMMIT();
    fill_ab(1, 64); CP_COMMIT();

    int sc = 0;
    for (int it = 0; it < nsteps; it++) {
        int sn = sc + 1; if (sn == 3) sn = 0;
        int sf = sn + 1; if (sf == 3) sf = 0;

        if (it < nsteps - 1)
            asm volatile("cp.async.wait_group 1;" ::: "memory");
        else
            asm volatile("cp.async.wait_group 0;" ::: "memory");
        __syncthreads();

        if (it + 2 < nsteps) { fill_ab(sf, (it + 2) * 64); CP_COMMIT(); }

        uint32_t base = sb + (uint32_t)sc * STG;
#pragma unroll
        for (int s = 0; s < 4; s++) {
            const int kk0 = s * 2;
            uint32_t af[2][2][4];
#pragma unroll
            for (int mt = 0; mt < 2; mt++) {
                int r2 = wm + mt * 16 + (lane & 15);
                int k2 = kk0 + (lane >> 4);
                uint32_t ad = off_km64(r2, k2);
                ldsm4(af[mt][0], base + ad);
                ldsm4(af[mt][1], base + 16384 + ad);
            }
            uint32_t bh[4][2], bl[4][2];
#pragma unroll
            for (int p = 0; p < 2; p++) {
                int r2 = wn + p * 16 + ((lane >> 4) << 3) + (lane & 7);
                int k2 = kk0 + ((lane >> 3) & 1);
                uint32_t bd = off_km64(r2, k2);
                uint32_t r[4];
                ldsm4(r, base + 32768 + bd);
                bh[2 * p][0] = r[0]; bh[2 * p][1] = r[1];
                bh[2 * p + 1][0] = r[2]; bh[2 * p + 1][1] = r[3];
                ldsm4(r, base + 49152 + bd);
                bl[2 * p][0] = r[0]; bl[2 * p][1] = r[1];
                bl[2 * p + 1][0] = r[2]; bl[2 * p + 1][1] = r[3];
            }
#pragma unroll
            for (int mt = 0; mt < 2; mt++)
#pragma unroll
                for (int nt = 0; nt < 4; nt++) {
                    mma_bf16(acc[mt][nt], af[mt][0], bh[nt]);
                    mma_bf16(acc[mt][nt], af[mt][0], bl[nt]);
                    mma_bf16(acc[mt][nt], af[mt][1], bh[nt]);
                }
        }
        sc = sn;
    }
    __syncthreads();

    float* sd = reinterpret_cast<float*>(smem);
#pragma unroll
    for (int mt = 0; mt < 2; mt++)
#pragma unroll
        for (int nt = 0; nt < 4; nt++) {
            int r = wm + mt * 16 + (lane >> 2);
            int c = wn + nt * 8 + (lane & 3) * 2;
            sd[r * 129 + c]           = acc[mt][nt][0];
            sd[r * 129 + c + 1]       = acc[mt][nt][1];
            sd[(r + 8) * 129 + c]     = acc[mt][nt][2];
            sd[(r + 8) * 129 + c + 1] = acc[mt][nt][3];
        }
    __syncthreads();

    if (mode == 1) {
        int mg = (tid & 31) * 4;
        int nl = tid >> 5;
        for (int n0 = 0; n0 < 128; n0 += 16) {
            int n = n0 + nl;
            uint2 vh, vl;
            __nv_bfloat16* hp = (__nv_bfloat16*)&vh;
            __nv_bfloat16* lp = (__nv_bfloat16*)&vl;
#pragma unroll
            for (int j = 0; j < 4; j++) {
                float v = sd[(mg + j) * 129 + n] + bias[bm + mg + j];
                __nv_bfloat16 h = __float2bfloat16(v);
                hp[j] = h;
                lp[j] = __float2bfloat16(v - __bfloat162float(h));
            }
            *reinterpret_cast<uint2*>(outHi + (size_t)(bn + n) * 2048 + bm + mg) = vh;
            *reinterpret_cast<uint2*>(outLo + (size_t)(bn + n) * 2048 + bm + mg) = vl;
        }
    } else {
        int mo = tid >> 7, n = tid & 127;
        int gn = bn + n;
        if (gn < T_LEN) {
            for (int m0 = 0; m0 < 128; m0 += 4) {
                int m = m0 + mo;
                outF[(size_t)(bm + m) * T_LEN + gn] = sd[m * 129 + n] + bias[bm + m];
            }
        }
    }
}

// ---------------- upsample GEMM (A fp32 w_up, fused combine epilogue) ---------------
__global__ __launch_bounds__(512)
void k_gemm_up(const float* __restrict__ Af32,
               const __nv_bfloat16* __restrict__ Bhi, const __nv_bfloat16* __restrict__ Blo,
               const float* __restrict__ bias,
               __nv_bfloat16* __restrict__ outHi, __nv_bfloat16* __restrict__ outLo)
{
    extern __shared__ char smem[];
    uint32_t sb = s2u(smem);
    const int tid = threadIdx.x;
    const int wid = tid >> 5, lane = tid & 31;
    const int Mg = 32768, K = 2048;
    const int bm = blockIdx.x * 128, bn = 0;
    const int wm = (wid & 3) * 32, wn = (wid >> 2) * 32;
    const uint32_t STG = 65536;

    float acc[2][4][4];
#pragma unroll
    for (int mt = 0; mt < 2; mt++)
#pragma unroll
        for (int nt = 0; nt < 4; nt++)
#pragma unroll
            for (int i = 0; i < 4; i++) acc[mt][nt][i] = 0.0f;

    const int nsteps = K >> 6;
    float4 pre[4];

    auto ldg_pre = [&](int k0) {
#pragma unroll
        for (int i = 0; i < 4; i++) {
            int u = tid + i * 512;
            int k = u >> 5, f4 = u & 31;
            pre[i] = *reinterpret_cast<const float4*>(Af32 + (size_t)(k0 + k) * Mg + bm + f4 * 4);
        }
    };
    auto sts_pre = [&](int s) {
#pragma unroll
        for (int i = 0; i < 4; i++) {
            int u = tid + i * 512;
            int k = u >> 5, f4 = u & 31;
            float4 v = pre[i];
            __nv_bfloat16 h0 = __float2bfloat16(v.x), h1 = __float2bfloat16(v.y);
            __nv_bfloat16 h2 = __float2bfloat16(v.z), h3 = __float2bfloat16(v.w);
            uint32_t hi01 = (uint32_t)__bfloat16_as_ushort(h0) |
                            ((uint32_t)__bfloat16_as_ushort(h1) << 16);
            uint32_t hi23 = (uint32_t)__bfloat16_as_ushort(h2) |
                            ((uint32_t)__bfloat16_as_ushort(h3) << 16);
            uint32_t lo01 = bpack(v.x - __bfloat162float(h0), v.y - __bfloat162float(h1));
            uint32_t lo23 = bpack(v.z - __bfloat162float(h2), v.w - __bfloat162float(h3));
            int mc = f4 >> 1, half = f4 & 1;
            uint32_t a = (uint32_t)s * STG + off_tr64(k, mc) + half * 8;
            *reinterpret_cast<uint2*>(smem + a) = make_uint2(hi01, hi23);
            *reinterpret_cast<uint2*>(smem + 16384 + a) = make_uint2(lo01, lo23);
        }
    };
    auto fill_b = [&](int s, int k0) {
        uint32_t base = sb + (uint32_t)s * STG;
#pragma unroll
        for (int i = 0; i < 2; i++) {
            int idx = tid + i * 512;
            int row = idx >> 3, kk = idx & 7;
            uint32_t d = off_km64(row, kk);
            cp16(base + 32768 + d, Bhi + (size_t)(bn + row) * K + k0 + kk * 8);
            cp16(base + 49152 + d, Blo + (size_t)(bn + row) * K + k0 + kk * 8);
        }
    };

    ldg_pre(0);
    sts_pre(0);
    ldg_pre(64);
    fill_b(0, 0);  CP_COMMIT();
    fill_b(1, 64); CP_COMMIT();

    int sc = 0;
    for (int it = 0; it < nsteps; it++) {
        int sn = sc + 1; if (sn == 3) sn = 0;
        int sf = sn + 1; if (sf == 3) sf = 0;

        if (it < nsteps - 1)
            asm volatile("cp.async.wait_group 1;" ::: "memory");
        else
            asm volatile("cp.async.wait_group 0;" ::: "memory");
        __syncthreads();

        if (it + 1 < nsteps) sts_pre(sn);
        if (it + 2 < nsteps) {
            ldg_pre((it + 2) * 64);
            fill_b(sf, (it + 2) * 64);
            CP_COMMIT();
        }

        uint32_t base = sb + (uint32_t)sc * STG;
#pragma unroll
        for (int s = 0; s < 4; s++) {
            const int kk0 = s * 2;
            uint32_t af[2][2][4];
#pragma unroll
            for (int mt = 0; mt < 2; mt++) {
                int k  = s * 16 + ((lane >> 4) << 3) + (lane & 7);
                int mc = ((wm + mt * 16) >> 3) + ((lane >> 3) & 1);
                uint32_t ad = off_tr64(k, mc);
                ldsm4t(af[mt][0], base + ad);
                ldsm4t(af[mt][1], base + 16384 + ad);
            }
            uint32_t bh[4][2], bl[4][2];
#pragma unroll
            for (int p = 0; p < 2; p++) {
                int r2 = wn + p * 16 + ((lane >> 4) << 3) + (lane & 7);
                int k2 = kk0 + ((lane >> 3) & 1);
                uint32_t bd = off_km64(r2, k2);
                uint32_t r[4];
                ldsm4(r, base + 32768 + bd);
                bh[2 * p][0] = r[0]; bh[2 * p][1] = r[1];
                bh[2 * p + 1][0] = r[2]; bh[2 * p + 1][1] = r[3];
                ldsm4(r, base + 49152 + bd);
                bl[2 * p][0] = r[0]; bl[2 * p][1] = r[1];
                bl[2 * p + 1][0] = r[2]; bl[2 * p + 1][1] = r[3];
            }
#pragma unroll
            for (int mt = 0; mt < 2; mt++)
#pragma unroll
                for (int nt = 0; nt < 4; nt++) {
                    mma_bf16(acc[mt][nt], af[mt][0], bh[nt]);
                    mma_bf16(acc[mt][nt], af[mt][0], bl[nt]);
                    mma_bf16(acc[mt][nt], af[mt][1], bh[nt]);
                }
        }
        sc = sn;
    }
    __syncthreads();

    float* sd = reinterpret_cast<float*>(smem);
#pragma unroll
    for (int mt = 0; mt < 2; mt++)
#pragma unroll
        for (int nt = 0; nt < 4; nt++) {
            int r = wm + mt * 16 + (lane >> 2);
            int c = wn + nt * 8 + (lane & 3) * 2;
            sd[r * 129 + c]           = acc[mt][nt][0];
            sd[r * 129 + c + 1]       = acc[mt][nt][1];
            sd[(r + 8) * 129 + c]     = acc[mt][nt][2];
            sd[(r + 8) * 129 + c + 1] = acc[mt][nt][3];
        }
    __syncthreads();

    // fused upsample-combine epilogue -> cond_raw^T hi/lo [1016][2048]
    int bo = bm >> 4;
    for (int u = tid; u < T_LEN; u += 512) {
        int m = u >> 3, p = u & 7;
        uint4 vh, vl;
        __nv_bfloat16* hp = (__nv_bfloat16*)&vh;
        __nv_bfloat16* lp = (__nv_bfloat16*)&vl;
#pragma unroll
        for (int ol = 0; ol < 8; ol++) {
            float v = sd[(ol * 16 + p + 8) * 129 + m] +
                      sd[(ol * 16 + p) * 129 + m + 1] + bias[bo + ol];
            __nv_bfloat16 h = __float2bfloat16(v);
            hp[ol] = h;
            lp[ol] = __float2bfloat16(v - __bfloat162float(h));
        }
        __nv_bfloat16* outHiP = outHi + (size_t)u * 2048 + bo;
        __nv_bfloat16* outLoP = outLo + (size_t)u * 2048 + bo;
        *reinterpret_cast<uint4*>(outHiP) = vh;
        *reinterpret_cast<uint4*>(outLoP) = vl;
    }
}

// ---------------- merged cond GEMMs (persistent, internal grid barrier) -------------
__global__ __launch_bounds__(512)
void k_cond2x(const float* __restrict__ b_cond)
{
    extern __shared__ char smem[];
    uint32_t sb = s2u(smem);
    const int tid = threadIdx.x;
    const int bm = blockIdx.x * 128, bn = blockIdx.y * 128;

    __nv_bfloat16* WC_HI = (__nv_bfloat16*)(g_scratch + OFF_WC_HI);
    __nv_bfloat16* WC_LO = (__nv_bfloat16*)(g_scratch + OFF_WC_LO);
    __nv_bfloat16* BR_HI = (__nv_bfloat16*)(g_scratch + OFF_BR_HI);
    __nv_bfloat16* BR_LO = (__nv_bfloat16*)(g_scratch + OFF_BR_LO);
    __nv_bfloat16* B2_HI = (__nv_bfloat16*)(g_scratch + OFF_B2_HI);
    __nv_bfloat16* B2_LO = (__nv_bfloat16*)(g_scratch + OFF_B2_LO);

    gemm_core(smem, sb, tid, WC_HI, WC_LO, BR_HI, BR_LO, 2048, bm, bn, 1,
              b_cond, nullptr, B2_HI, B2_LO);

    // grid barrier across all 128 blocks
    __syncthreads();
    __threadfence();
    if (tid == 0) {
        atomicAdd(&g_bar2, 1u);
        unsigned v;
        do {
            asm volatile("ld.global.acquire.gpu.u32 %0, [%1];"
                         : "=r"(v) : "l"(&g_bar2) : "memory");
        } while (v < 128u);
    }
    __syncthreads();

    gemm_core(smem, sb, tid, WC_HI, WC_LO, B2_HI, B2_LO, 2048, bm, bn, 2,
              b_cond, g_scratch + OFF_CACTS, nullptr, nullptr);
}

// ---------------- fused persistent tail ---------------------------------------------
__global__ __launch_bounds__(256)
void k_tail(const float* __restrict__ audio, const float* __restrict__ embed,
            const float* __restrict__ w_dil_all, const float* __restrict__ b_dil_all,
            const float* __restrict__ b_res_all, const float* __restrict__ b_skip_all,
            float* __restrict__ out, int write_q)
{
    extern __shared__ float sm[];
    float2* WDp = reinterpret_cast<float2*>(sm);   // 8192 float2 (64KB): [j][c] tap pairs
    float* XS0 = sm + 16384;
    float* XS1 = XS0 + 512;
    float* IA  = XS1 + 512;
    float* ACT = IA + 512;
    float* HS  = ACT + 512;
    float* HS2 = HS + 2048;
    int*   QS  = (int*)(HS2 + 2048);

    const int tid = threadIdx.x;
    const int t0 = blockIdx.x * TB;

    // ---- mu-law encode ----
    if (tid < TB) {
        int t = t0 + tid;
        float x = audio[t];
        float xc = fminf(1.0f, fmaxf(-1.0f, x));
        float s  = (xc > 0.0f) ? 1.0f : ((xc < 0.0f) ? -1.0f : 0.0f);
        float num = log1pf(__fmul_rn(255.0f, fabsf(xc)));
        float den = log1pf(255.0f);
        float m = __fdiv_rn(__fmul_rn(s, num), den);
        float v = __fadd_rn(__fmul_rn(__fmul_rn(__fadd_rn(m, 1.0f), 0.5f), 255.0f), 0.5f);
        v = fminf(255.0f, fmaxf(0.0f, v));
        int q = (int)v;
        QS[tid] = q;
        if (write_q) out[(size_t)256 * T_LEN + t] = (float)q;
    }
    __syncthreads();

    // ---- embedding -> X0, then arrive ----
    {
        float* X0 = g_scratch + OFF_X0;
        for (int idx = tid; idx < 64 * TB; idx += 256) {
            int j = idx / TB, tt = idx % TB;
            X0[(size_t)j * T_LEN + t0 + tt] = embed[QS[tt] * 64 + j];
        }
    }
    __threadfence();
    __syncthreads();
    if (tid == 0) atomicAdd(&g_bar, 1u);

    float s_acc[TB];
#pragma unroll
    for (int tt = 0; tt < TB; tt++) s_acc[tt] = 0.0f;

    const int c  = tid & 127;
    const int th = tid >> 7;
    unsigned target = NBLK;

    for (int layer = 0; layer < 16; layer++) {
        const int d = 1 << (layer & 7);
        const float* xin  = g_scratch + ((layer & 1) ? OFF_X1 : OFF_X0);
        float*       xout = g_scratch + ((layer & 1) ? OFF_X0 : OFF_X1);
        const float* cond = g_scratch + OFF_CACTS + (size_t)layer * 128 * T_LEN;
        const float2* wd2 = reinterpret_cast<const float2*>(w_dil_all + (size_t)layer * 16384);

        // stage full layer weights as (w0,w1) pairs: WDp[j*128 + cc]
        for (int idx = tid; idx < 8192; idx += 256) {
            int cc = idx >> 6, j = idx & 63;
            WDp[j * 128 + cc] = wd2[idx];
        }

        // wait: all blocks finished previous layer writes
        if (tid == 0) {
            unsigned v;
            do {
                asm volatile("ld.global.acquire.gpu.u32 %0, [%1];"
                             : "=r"(v) : "l"(&g_bar) : "memory");
            } while (v < target);
        }
        __syncthreads();
        target += NBLK;

        // stage x windows
        for (int idx = tid; idx < 64 * TB; idx += 256) {
            int j = idx >> 3, tt = idx & 7;
            int ta = t0 - d + tt;
            XS0[idx] = (ta >= 0) ? xin[(size_t)j * T_LEN + ta] : 0.0f;
            XS1[idx] = xin[(size_t)j * T_LEN + t0 + tt];
        }
        __syncthreads();

        // dilated conv: 64 j, 2 taps, 4 t per thread
        float a4[4] = {0.0f, 0.0f, 0.0f, 0.0f};
#pragma unroll
        for (int j = 0; j < 64; j++) {
            float2 w = WDp[j * 128 + c];
            float4 x0 = *reinterpret_cast<const float4*>(&XS0[j * TB + th * 4]);
            float4 x1 = *reinterpret_cast<const float4*>(&XS1[j * TB + th * 4]);
            a4[0] += w.x * x0.x + w.y * x1.x;
            a4[1] += w.x * x0.y + w.y * x1.y;
            a4[2] += w.x * x0.z + w.y * x1.z;
            a4[3] += w.x * x0.w + w.y * x1.w;
        }

        {
            float bd = b_dil_all[layer * 128 + c];
#pragma unroll
            for (int i = 0; i < 4; i++) {
                int t = t0 + th * 4 + i;
                a4[i] += bd + cond[(size_t)c * T_LEN + t];
            }
        }
        __syncthreads();
        if (c >= 64) {
#pragma unroll
            for (int i = 0; i < 4; i++) IA[(c - 64) * TB + th * 4 + i] = a4[i];
        }
        __syncthreads();
        if (c < 64) {
#pragma unroll
            for (int i = 0; i < 4; i++) {
                int tt = th * 4 + i;
                float g = IA[c * TB + tt];
                float sg = 1.0f / (1.0f + expf(-g));
                ACT[c * TB + tt] = tanhf(a4[i]) * sg;
            }
        }
        __syncthreads();

        // residual write, then EARLY arrive (skip GEMM overlaps barrier latency)
        if (layer < 15) {
            const float* wr = g_scratch + OFF_WRST + (size_t)layer * 4096;
            int c2 = tid & 63, qq = tid >> 6;
            float r2[2] = {0.0f, 0.0f};
#pragma unroll 8
            for (int k = 0; k < 64; k++) {
                float w = wr[k * 64 + c2];
                r2[0] += w * ACT[k * TB + qq * 2];
                r2[1] += w * ACT[k * TB + qq * 2 + 1];
            }
            float br = b_res_all[layer * 64 + c2];
#pragma unroll
            for (int i = 0; i < 2; i++) {
                int t = t0 + qq * 2 + i;
                xout[(size_t)c2 * T_LEN + t] = xin[(size_t)c2 * T_LEN + t] + r2[i] + br;
            }
            __threadfence();
            __syncthreads();
            if (tid == 0) atomicAdd(&g_bar, 1u);
        }

        // skip accumulation (row = tid), overlapped with other blocks' progress
        {
            const float* wsk = g_scratch + OFF_WSKT + (size_t)layer * 16384;
#pragma unroll 8
            for (int k = 0; k < 64; k++) {
                float w = wsk[k * 256 + tid];
                float4 a0 = *reinterpret_cast<const float4*>(&ACT[k * TB]);
                float4 a1 = *reinterpret_cast<const float4*>(&ACT[k * TB + 4]);
                s_acc[0] += w * a0.x; s_acc[1] += w * a0.y;
                s_acc[2] += w * a0.z; s_acc[3] += w * a0.w;
                s_acc[4] += w * a1.x; s_acc[5] += w * a1.y;
                s_acc[6] += w * a1.z; s_acc[7] += w * a1.w;
            }
            float bs = b_skip_all[layer * 256 + tid];
#pragma unroll
            for (int tt = 0; tt < TB; tt++) s_acc[tt] += bs;
        }
    }

    // ---- heads (block-local) ----
    {
        __syncthreads();
#pragma unroll
        for (int tt = 0; tt < TB; tt++) HS[tid * TB + tt] = fmaxf(s_acc[tt], 0.0f);
        __syncthreads();

        const float* wo = g_scratch + OFF_WOT;
        float h[TB];
#pragma unroll
        for (int tt = 0; tt < TB; tt++) h[tt] = 0.0f;
        for (int cc = 0; cc < 256; cc++) {
            float w = wo[cc * 256 + tid];
            float4 v0 = *reinterpret_cast<const float4*>(&HS[cc * TB]);
            float4 v1 = *reinterpret_cast<const float4*>(&HS[cc * TB + 4]);
            h[0] += w * v0.x; h[1] += w * v0.y; h[2] += w * v0.z; h[3] += w * v0.w;
            h[4] += w * v1.x; h[5] += w * v1.y; h[6] += w * v1.z; h[7] += w * v1.w;
        }
#pragma unroll
        for (int tt = 0; tt < TB; tt++) HS2[tid * TB + tt] = fmaxf(h[tt], 0.0f);
        __syncthreads();

        const float* we = g_scratch + OFF_WET;
        float h2[TB];
#pragma unroll
        for (int tt = 0; tt < TB; tt++) h2[tt] = 0.0f;
        for (int cc = 0; cc < 256; cc++) {
            float w = we[cc * 256 + tid];
            float4 v0 = *reinterpret_cast<const float4*>(&HS2[cc * TB]);
            float4 v1 = *reinterpret_cast<const float4*>(&HS2[cc * TB + 4]);
            h2[0] += w * v0.x; h2[1] += w * v0.y; h2[2] += w * v0.z; h2[3] += w * v0.w;
            h2[4] += w * v1.x; h2[5] += w * v1.y; h2[6] += w * v1.z; h2[7] += w * v1.w;
        }

        if (blockIdx.x == 0) out[(size_t)tid * T_LEN] = 0.0f;
#pragma unroll
        for (int tt = 0; tt < TB; tt++) {
            int t = t0 + tt;
            if (t + 1 < T_LEN) out[(size_t)tid * T_LEN + t + 1] = h2[tt];
        }
    }
}

// ---------------- launch -------------------------------------------------------------
extern "C" void kernel_launch(void* const* d_in, const int* in_sizes, int n_in,
                              void* d_out, int out_size)
{
    const float* features = (const float*)d_in[0];
    const float* audio    = (const float*)d_in[1];
    const float* w_up     = (const float*)d_in[2];
    const float* b_up     = (const float*)d_in[3];
    const float* w_cond   = (const float*)d_in[4];
    const float* b_cond   = (const float*)d_in[5];
    const float* embed    = (const float*)d_in[6];
    const float* w_dil    = (const float*)d_in[7];
    const float* b_dil    = (const float*)d_in[8];
    const float* w_res    = (const float*)d_in[9];
    const float* b_res    = (const float*)d_in[10];
    const float* w_skip   = (const float*)d_in[11];
    const float* b_skip   = (const float*)d_in[12];
    const float* w_out    = (const float*)d_in[13];
    const float* w_end    = (const float*)d_in[14];
    float* out = (float*)d_out;

    float* scr = nullptr;
    cudaGetSymbolAddress((void**)&scr, g_scratch);

    __nv_bfloat16* FT_HI = (__nv_bfloat16*)(scr + OFF_FT_HI);
    __nv_bfloat16* FT_LO = (__nv_bfloat16*)(scr + OFF_FT_LO);
    __nv_bfloat16* BR_HI = (__nv_bfloat16*)(scr + OFF_BR_HI);
    __nv_bfloat16* BR_LO = (__nv_bfloat16*)(scr + OFF_BR_LO);

    cudaFuncSetAttribute(k_gemm_up, cudaFuncAttributeMaxDynamicSharedMemorySize, 196608);
    cudaFuncSetAttribute(k_cond2x, cudaFuncAttributeMaxDynamicSharedMemorySize, 196608);
    cudaFuncSetAttribute(k_tail, cudaFuncAttributeMaxDynamicSharedMemorySize, 92160);

    int write_q = (out_size >= 256 * T_LEN + T_LEN) ? 1 : 0;

    // [1] all prep (splits, transposes, barrier resets)
    k_prep<<<4797, 256>>>(features, w_cond, w_out, w_end, w_skip, w_res);
    // [2] upsample GEMM + fused combine
    k_gemm_up<<<dim3(256, 1), 512, 196608>>>(w_up, FT_HI, FT_LO, b_up, BR_HI, BR_LO);
    // [3] both cond GEMMs, persistent with internal grid barrier
    k_cond2x<<<dim3(16, 8), 512, 196608>>>(b_cond);
    // [4] fused persistent tail (ncu -s 5 -c 1 profiles this one)
    k_tail<<<NBLK, 256, 92160>>>(audio, embed, w_dil, b_dil, b_res, b_skip, out, write_q);
}